// round 13
// baseline (speedup 1.0000x reference)
#include <cuda_runtime.h>
#include <cuda_bf16.h>
#include <cuda_fp16.h>
#include <cstdint>

#define Bsz 4
#define Ssz 4096
#define Dsz 1024
#define Hh  8
#define Mm  32
#define Ww  16
#define NSs 128
#define GHh 128
#define TEMP 0.6f
#define SIGMA 0.12f
#define ALPHA 6.0f

#define HB (Hh*Bsz)          // 32
#define BS (Bsz*Ssz)         // 16384

#define A_SCALE 4096.0f
#define B_SCALE 64.0f
#define INV_SCALE (1.0f/(A_SCALE*B_SCALE))

// ---------------- scratch (static device globals; no allocation) ------------
__device__ float g_pooled[Bsz*Dsz];        // [B, D]
__device__ float g_hpre[Hh*Bsz*GHh];       // [H, B, GH] relu hidden
__device__ float g_weights[Hh*Bsz*Mm];     // [H, B, M]  (softmax weights)
__device__ float g_mask[Hh*Mm*Ssz];        // [H, M, S]
__device__ float g_dens[HB*Ssz];           // [hb][s] unnormalized density
__device__ float g_dsum[HB];               // per (h,b) sum over S
__device__ float g_W1T[Hh*GHh*Dsz];        // W1 transposed [h][g][d]
__device__ uint8_t g_Wo8[Dsz*Dsz];         // Wo^T [n][k], e4m3, x64
__device__ uint8_t g_A8[(size_t)BS*Dsz];   // A' = x*density*4096, e4m3 [r][k]

// ---------------- helpers -----------------------------------------------------
__device__ __forceinline__ uint32_t pack_fp8x4(float f0, float f1, float f2, float f3) {
    unsigned short lo, hi;
    asm("cvt.rn.satfinite.e4m3x2.f32 %0, %1, %2;" : "=h"(lo) : "f"(f1), "f"(f0));
    asm("cvt.rn.satfinite.e4m3x2.f32 %0, %1, %2;" : "=h"(hi) : "f"(f3), "f"(f2));
    return (uint32_t)lo | ((uint32_t)hi << 16);
}

// ---------------- kernel 0: zero accumulators --------------------------------
__global__ void init_kernel() {
    int i = blockIdx.x * 256 + threadIdx.x;
    if (i < Bsz*Dsz) g_pooled[i] = 0.f;
    if (i < HB)      g_dsum[i]   = 0.f;
}

// ---------------- kernel 1: pooled = x.mean(axis=1) --------------------------
__global__ void pooled_kernel(const float* __restrict__ x) {
    const int b = blockIdx.x;
    const int c = blockIdx.y;               // s-chunk of 128
    for (int d = threadIdx.x; d < Dsz; d += 256) {
        const float* p = x + (b*Ssz + c*128)*Dsz + d;
        float acc = 0.f;
        #pragma unroll 4
        for (int s = 0; s < 128; s++) acc += p[s*Dsz];
        atomicAdd(&g_pooled[b*Dsz + d], acc * (1.0f/(float)Ssz));
    }
}

// ---------------- kernel 1b: transpose W1 [h,d,g] -> [h,g,d] ------------------
__global__ void w1t_kernel(const float* __restrict__ W1) {
    __shared__ float t[32][33];
    const int h = blockIdx.z;
    const int g0 = blockIdx.x * 32, d0 = blockIdx.y * 32;
    const int tx = threadIdx.x & 31, ty = threadIdx.x >> 5;   // 32 x 8
    #pragma unroll
    for (int i = 0; i < 32; i += 8)
        t[ty + i][tx] = W1[h*Dsz*GHh + (d0 + ty + i)*GHh + g0 + tx];
    __syncthreads();
    #pragma unroll
    for (int i = 0; i < 32; i += 8)
        g_W1T[h*GHh*Dsz + (g0 + ty + i)*Dsz + d0 + tx] = t[tx][ty + i];
}

// ---------------- kernel 2a: hpre = relu(pooled @ W1 + b1) -------------------
__global__ void gate1_kernel(const float* __restrict__ b1) {
    const int h = blockIdx.x >> 7, g = blockIdx.x & 127;
    const int b = threadIdx.x >> 5, lane = threadIdx.x & 31;
    const float* w = g_W1T + (h*GHh + g)*Dsz;
    const float* p = g_pooled + b*Dsz;
    float a0 = 0.f, a1 = 0.f, a2 = 0.f, a3 = 0.f;
    #pragma unroll
    for (int d = lane; d < Dsz; d += 128) {
        a0 = fmaf(p[d      ], w[d      ], a0);
        a1 = fmaf(p[d + 32 ], w[d + 32 ], a1);
        a2 = fmaf(p[d + 64 ], w[d + 64 ], a2);
        a3 = fmaf(p[d + 96 ], w[d + 96 ], a3);
    }
    float acc = (a0 + a1) + (a2 + a3);
    #pragma unroll
    for (int o = 16; o; o >>= 1) acc += __shfl_xor_sync(0xffffffffu, acc, o);
    if (lane == 0)
        g_hpre[(h*Bsz + b)*GHh + g] = fmaxf(acc + b1[h*GHh + g], 0.f);
}

// ---------------- kernel 2b: logits = hpre @ W2 + b2; softmax ----------------
__global__ void gate2_kernel(const float* __restrict__ W2, const float* __restrict__ b2) {
    const int h = blockIdx.x >> 2, b = blockIdx.x & 3;
    const int t = threadIdx.x;
    __shared__ float sh[GHh];
    __shared__ float part[128];
    sh[t] = g_hpre[(h*Bsz + b)*GHh + t];
    __syncthreads();
    const int m = t & 31, c = t >> 5;
    float acc = 0.f;
    #pragma unroll 8
    for (int i = 0; i < 32; i++) {
        const int g = c*32 + i;
        acc = fmaf(sh[g], W2[(h*GHh + g)*Mm + m], acc);
    }
    part[t] = acc;
    __syncthreads();
    if (t < 32) {
        float l = part[t] + part[t+32] + part[t+64] + part[t+96] + b2[h*Mm + t];
        float z = l * (1.0f/TEMP);
        float mx = z;
        #pragma unroll
        for (int o = 16; o; o >>= 1) mx = fmaxf(mx, __shfl_xor_sync(0xffffffffu, mx, o));
        float e = __expf(z - mx);
        float sm = e;
        #pragma unroll
        for (int o = 16; o; o >>= 1) sm += __shfl_xor_sync(0xffffffffu, sm, o);
        g_weights[(h*Bsz + b)*Mm + t] = e / sm;
    }
}

// ---------------- kernel 3: mask grids [H, M, S] ------------------------------
__global__ void mask_kernel(const float* __restrict__ freqs, const float* __restrict__ amps,
                            const float* __restrict__ phases) {
    const int hm = blockIdx.x;
    __shared__ float fx[Ww], fy[Ww], am[Ww], ph[Ww];
    if (threadIdx.x < Ww) {
        int w = threadIdx.x;
        fx[w] = freqs[(hm*Ww + w)*2 + 0];
        fy[w] = freqs[(hm*Ww + w)*2 + 1];
        am[w] = amps[hm*Ww + w];
        ph[w] = phases[hm*Ww + w];
    }
    __syncthreads();
    const float TWO_PI   = 6.28318530717958647692f;
    const float HALF_PI  = 1.57079632679489661923f;
    const float INV_2PI  = 0.15915494309189533577f;
    for (int s = threadIdx.x; s < Ssz; s += 256) {
        const int i = s >> 6, j = s & 63;
        const float px = -1.f + (float)j * (2.f/63.f);
        const float py = -1.f + (float)i * (2.f/63.f);
        float acc = 0.f;
        #pragma unroll
        for (int w = 0; w < Ww; w++) {
            float dot = fmaf(px, fx[w], py*fy[w]);
            float arg = fmaf(TWO_PI, dot, ph[w]);
            float t   = (arg - HALF_PI) * INV_2PI;
            float fr  = t - floorf(t);
            float tri01 = 1.f - 2.f*fabsf(fr - 0.5f);
            acc = fmaf(2.f*tri01 - 1.f, am[w], acc);
        }
        g_mask[hm*Ssz + s] = acc;
    }
}

// ---------------- kernel 4: final_grid + MC density (fused) -------------------
__global__ void density_kernel(const float* __restrict__ noise) {
    const int hb = blockIdx.y;
    const int h  = hb >> 2;
    const int s  = blockIdx.x*256 + threadIdx.x;
    __shared__ float wts[Mm];
    if (threadIdx.x < Mm) wts[threadIdx.x] = g_weights[hb*Mm + threadIdx.x];
    __syncthreads();

    const float* mk = g_mask + (h*Mm)*Ssz + s;
    float fg = 0.f;
    #pragma unroll
    for (int m = 0; m < Mm; m++) fg = fmaf(wts[m], mk[m*Ssz], fg);

    const float hfg = 0.5f * ALPHA * fg;
    const float hsn = 0.5f * ALPHA * SIGMA;
    const float* np = noise + (hb*NSs)*Ssz + s;
    float acc = 0.f;
    #pragma unroll 4
    for (int ns = 0; ns < NSs; ns++) {
        float z = fmaf(np[ns*Ssz], hsn, hfg);
        float t;
        asm("tanh.approx.f32 %0, %1;" : "=f"(t) : "f"(z));
        acc += t;
    }
    float dens = fmaf(acc, 0.5f/(float)NSs, 0.5f);
    g_dens[hb*Ssz + s] = dens;

    float v = dens;
    #pragma unroll
    for (int o = 16; o; o >>= 1) v += __shfl_xor_sync(0xffffffffu, v, o);
    __shared__ float red[8];
    if ((threadIdx.x & 31) == 0) red[threadIdx.x >> 5] = v;
    __syncthreads();
    if (threadIdx.x < 8) {
        float t = red[threadIdx.x];
        #pragma unroll
        for (int o = 4; o; o >>= 1) t += __shfl_xor_sync(0xffu, t, o);
        if (threadIdx.x == 0) atomicAdd(&g_dsum[hb], t);
    }
}

// ---------------- kernel 5: A' = x * dnorm * 4096 -> e4m3 ---------------------
__global__ void aprep8_kernel(const float* __restrict__ x) {
    const int gid = blockIdx.x*256 + threadIdx.x;     // BS*64 granules
    const int r = gid >> 6, g = gid & 63;             // row, k-granule (16 k each)
    const int hb = (g >> 3)*Bsz + (r >> 12);          // h = g>>3
    const float sc = g_dens[hb*Ssz + (r & 4095)] / (g_dsum[hb] + 1e-8f) * A_SCALE;
    const float4* xp = reinterpret_cast<const float4*>(x + (size_t)gid*16);
    float4 v0 = xp[0], v1 = xp[1], v2 = xp[2], v3 = xp[3];
    uint4 pk;
    pk.x = pack_fp8x4(v0.x*sc, v0.y*sc, v0.z*sc, v0.w*sc);
    pk.y = pack_fp8x4(v1.x*sc, v1.y*sc, v1.z*sc, v1.w*sc);
    pk.z = pack_fp8x4(v2.x*sc, v2.y*sc, v2.z*sc, v2.w*sc);
    pk.w = pack_fp8x4(v3.x*sc, v3.y*sc, v3.z*sc, v3.w*sc);
    *reinterpret_cast<uint4*>(g_A8 + (size_t)gid*16) = pk;
}

// ---------------- kernel 5b: transpose + convert Wo -> e4m3 [n][k], x64 -------
__global__ void wot8_kernel(const float* __restrict__ Wo) {
    __shared__ float t[32][33];
    const int n0 = blockIdx.x * 32, k0 = blockIdx.y * 32;
    const int tx = threadIdx.x & 31, ty = threadIdx.x >> 5;
    #pragma unroll
    for (int i = 0; i < 32; i += 8)
        t[ty + i][tx] = Wo[(k0 + ty + i)*Dsz + n0 + tx];
    __syncthreads();
    #pragma unroll
    for (int i = 0; i < 32; i += 8) {
        float v = t[tx][ty + i] * B_SCALE;
        unsigned short p;
        asm("cvt.rn.satfinite.e4m3x2.f32 %0, %1, %2;" : "=h"(p) : "f"(0.f), "f"(v));
        g_Wo8[(size_t)(n0 + ty + i)*Dsz + k0 + tx] = (uint8_t)(p & 0xFF);
    }
}

// ---------------- kernel 6: fp8 QMMA GEMM (fp16 accum), BK=128 ----------------
// out[r,n] = (1/SCALE) * sum_k A8[r,k]*Wo8[n,k] + bo[n] + x[r,n]
// 128x128 tile, BK=128 fp8, double-buffered, 1 barrier/tile, B via ldmatrix.x4
#define BKP8 144           // padded k-stride (16B-aligned; 36r mod 32 conflict-free)
#define NKT8 (Dsz/128)     // 8 k-tiles
#define BUF_A (128*BKP8)   // 18432 bytes
#define BUF_STAGE (2*BUF_A)        // A + B per stage = 36864
#define SMEM_GEMM (2*BUF_STAGE)    // 73728

__global__ __launch_bounds__(256) void gemm_fp8_kernel(const float* __restrict__ x,
                                                       const float* __restrict__ bo,
                                                       float* __restrict__ out) {
    extern __shared__ __align__(16) uint8_t dsm[];
    const int tid  = threadIdx.x;
    const int lane = tid & 31, warp = tid >> 5;
    const int mbase = (warp >> 2) * 64;          // warp grid 2 (m) x 4 (n)
    const int nbase = (warp & 3) * 32;
    const int rowBase = blockIdx.y * 128;
    const int colBase = blockIdx.x * 128;

    const int rA = tid >> 1;                     // loader row (0..127)
    const int halfA = tid & 1;                   // which 64-byte half
    const uint8_t* arow = g_A8  + (size_t)(rowBase + rA)*Dsz + halfA*64;
    const uint8_t* brow = g_Wo8 + (size_t)(colBase + rA)*Dsz + halfA*64;

    const uint32_t sBase = (uint32_t)__cvta_generic_to_shared(dsm);
    const uint32_t stR = rA*BKP8 + halfA*64;     // staging offset within buffer

    // ldmatrix lane address components
    const int lmA_row = mbase + (lane & 15);             // + mi*16
    const int lmA_colB = (lane >> 4) << 4;               // 0 or 16
    // B x4: lane groups 0..3 -> (n+0..7,kB),(n+0..7,kB+16),(n+8..15,kB),(n+8..15,kB+16)
    const int grp = lane >> 3;
    const int lmB_row = nbase + (grp >> 1)*8 + (lane & 7);   // + pair*16
    const int lmB_colB = (grp & 1) << 4;                     // 0 or 16

    uint4 va[4], vb[4];

    // prologue: tile 0 -> smem buf 0
    {
        const uint4* ap = reinterpret_cast<const uint4*>(arow);
        const uint4* bp = reinterpret_cast<const uint4*>(brow);
        #pragma unroll
        for (int j = 0; j < 4; j++) { va[j] = ap[j]; vb[j] = bp[j]; }
        uint4* as = reinterpret_cast<uint4*>(dsm + stR);
        uint4* bs = reinterpret_cast<uint4*>(dsm + BUF_A + stR);
        #pragma unroll
        for (int j = 0; j < 4; j++) { as[j] = va[j]; bs[j] = vb[j]; }
    }
    __syncthreads();
    {
        const uint4* ap = reinterpret_cast<const uint4*>(arow + 128);
        const uint4* bp = reinterpret_cast<const uint4*>(brow + 128);
        #pragma unroll
        for (int j = 0; j < 4; j++) { va[j] = ap[j]; vb[j] = bp[j]; }
    }

    // fp16 accumulators
    uint32_t acc[4][4][2];
    #pragma unroll
    for (int mi = 0; mi < 4; mi++)
        #pragma unroll
        for (int ni = 0; ni < 4; ni++) { acc[mi][ni][0] = 0u; acc[mi][ni][1] = 0u; }

    for (int t = 0; t < NKT8; t++) {
        const int cur = t & 1;
        if (t + 1 < NKT8) {
            uint4* as = reinterpret_cast<uint4*>(dsm + (cur^1)*BUF_STAGE + stR);
            uint4* bs = reinterpret_cast<uint4*>(dsm + (cur^1)*BUF_STAGE + BUF_A + stR);
            #pragma unroll
            for (int j = 0; j < 4; j++) { as[j] = va[j]; bs[j] = vb[j]; }
        }
        if (t + 2 < NKT8) {
            const uint4* ap = reinterpret_cast<const uint4*>(arow + (t+2)*128);
            const uint4* bp = reinterpret_cast<const uint4*>(brow + (t+2)*128);
            #pragma unroll
            for (int j = 0; j < 4; j++) { va[j] = ap[j]; vb[j] = bp[j]; }
        }
        const uint32_t aBase = sBase + cur*BUF_STAGE;
        const uint32_t bBase = aBase + BUF_A;
        #pragma unroll
        for (int ks = 0; ks < 4; ks++) {
            const int kB = ks * 32;              // k32 step
            uint32_t a[4][4], b[4][2];
            #pragma unroll
            for (int mi = 0; mi < 4; mi++) {
                uint32_t addr = aBase + (lmA_row + mi*16)*BKP8 + kB + lmA_colB;
                asm volatile("ldmatrix.sync.aligned.m8n8.x4.shared.b16 {%0,%1,%2,%3}, [%4];"
                             : "=r"(a[mi][0]), "=r"(a[mi][1]), "=r"(a[mi][2]), "=r"(a[mi][3])
                             : "r"(addr));
            }
            #pragma unroll
            for (int pr = 0; pr < 2; pr++) {     // ni pairs (2pr, 2pr+1)
                uint32_t addr = bBase + (lmB_row + pr*16)*BKP8 + kB + lmB_colB;
                asm volatile("ldmatrix.sync.aligned.m8n8.x4.shared.b16 {%0,%1,%2,%3}, [%4];"
                             : "=r"(b[2*pr][0]), "=r"(b[2*pr][1]),
                               "=r"(b[2*pr+1][0]), "=r"(b[2*pr+1][1])
                             : "r"(addr));
            }
            #pragma unroll
            for (int mi = 0; mi < 4; mi++)
                #pragma unroll
                for (int ni = 0; ni < 4; ni++) {
                    asm volatile(
                        "mma.sync.aligned.m16n8k32.row.col.f16.e4m3.e4m3.f16 "
                        "{%0,%1}, {%2,%3,%4,%5}, {%6,%7}, {%0,%1};"
                        : "+r"(acc[mi][ni][0]), "+r"(acc[mi][ni][1])
                        : "r"(a[mi][0]), "r"(a[mi][1]), "r"(a[mi][2]), "r"(a[mi][3]),
                          "r"(b[ni][0]), "r"(b[ni][1]));
                }
        }
        __syncthreads();
    }

    // --- epilogue: unpack fp16 acc, unscale + bo + x (residual) ---
    const int fr = lane >> 2;
    const int fc = (lane & 3) * 2;
    #pragma unroll
    for (int mi = 0; mi < 4; mi++) {
        const int r0 = rowBase + mbase + mi*16 + fr;
        #pragma unroll
        for (int ni = 0; ni < 4; ni++) {
            const int c0 = colBase + nbase + ni*8 + fc;
            float2 bov = *reinterpret_cast<const float2*>(bo + c0);
            float2 x0  = *reinterpret_cast<const float2*>(x + (size_t)r0*Dsz + c0);
            float2 x1  = *reinterpret_cast<const float2*>(x + (size_t)(r0+8)*Dsz + c0);
            __half2 h0 = *reinterpret_cast<__half2*>(&acc[mi][ni][0]);
            __half2 h1 = *reinterpret_cast<__half2*>(&acc[mi][ni][1]);
            float2 f0 = __half22float2(h0);
            float2 f1 = __half22float2(h1);
            float2 o0, o1;
            o0.x = f0.x*INV_SCALE + bov.x + x0.x;
            o0.y = f0.y*INV_SCALE + bov.y + x0.y;
            o1.x = f1.x*INV_SCALE + bov.x + x1.x;
            o1.y = f1.y*INV_SCALE + bov.y + x1.y;
            *reinterpret_cast<float2*>(out + (size_t)r0*Dsz + c0)     = o0;
            *reinterpret_cast<float2*>(out + (size_t)(r0+8)*Dsz + c0) = o1;
        }
    }
}

// ---------------- launcher ----------------------------------------------------
extern "C" void kernel_launch(void* const* d_in, const int* in_sizes, int n_in,
                              void* d_out, int out_size) {
    const float* x      = (const float*)d_in[0];
    const float* noise  = (const float*)d_in[1];
    const float* W1     = (const float*)d_in[2];
    const float* b1     = (const float*)d_in[3];
    const float* W2     = (const float*)d_in[4];
    const float* b2     = (const float*)d_in[5];
    const float* freqs  = (const float*)d_in[6];
    const float* amps   = (const float*)d_in[7];
    const float* phases = (const float*)d_in[8];
    const float* Wo     = (const float*)d_in[9];
    const float* bo     = (const float*)d_in[10];
    float* out = (float*)d_out;

    cudaFuncSetAttribute(gemm_fp8_kernel,
                         cudaFuncAttributeMaxDynamicSharedMemorySize, SMEM_GEMM);

    init_kernel    <<<16, 256>>>();
    pooled_kernel  <<<dim3(Bsz, 32), 256>>>(x);
    wot8_kernel    <<<dim3(32, 32), 256>>>(Wo);
    w1t_kernel     <<<dim3(4, 32, 8), 256>>>(W1);
    gate1_kernel   <<<Hh*GHh, 128>>>(b1);
    gate2_kernel   <<<Hh*Bsz, 128>>>(W2, b2);
    mask_kernel    <<<Hh*Mm, 256>>>(freqs, amps, phases);
    density_kernel <<<dim3(Ssz/256, HB), 256>>>(noise);
    aprep8_kernel  <<<(BS*64)/256, 256>>>(x);
    gemm_fp8_kernel<<<dim3(Dsz/128, BS/128), 256, SMEM_GEMM>>>(x, bo, out);
}

// round 14
// speedup vs baseline: 1.0067x; 1.0067x over previous
#include <cuda_runtime.h>
#include <cuda_bf16.h>
#include <cuda_fp16.h>
#include <cstdint>

#define Bsz 4
#define Ssz 4096
#define Dsz 1024
#define Hh  8
#define Mm  32
#define Ww  16
#define NSs 128
#define GHh 128
#define TEMP 0.6f
#define SIGMA 0.12f
#define ALPHA 6.0f

#define HB (Hh*Bsz)          // 32
#define BS (Bsz*Ssz)         // 16384

#define A_SCALE 4096.0f
#define B_SCALE 64.0f
#define INV_SCALE (1.0f/(A_SCALE*B_SCALE))

// ---------------- scratch (static device globals; no allocation) ------------
__device__ float g_pooled[Bsz*Dsz];        // [B, D]
__device__ float g_hpre[Hh*Bsz*GHh];       // [H, B, GH] relu hidden
__device__ float g_weights[Hh*Bsz*Mm];     // [H, B, M]  (softmax weights)
__device__ float g_mask[Hh*Mm*Ssz];        // [H, M, S]
__device__ float g_dens[HB*Ssz];           // [hb][s] unnormalized density
__device__ float g_dsum[HB];               // per (h,b) sum over S
__device__ float g_W1T[Hh*GHh*Dsz];        // W1 transposed [h][g][d]
__device__ uint8_t g_Wo8[Dsz*Dsz];         // Wo^T [n][k], e4m3, x64
__device__ uint8_t g_A8[(size_t)BS*Dsz];   // A' = x*density*4096, e4m3 [r][k]

// ---------------- helpers -----------------------------------------------------
__device__ __forceinline__ uint32_t pack_fp8x4(float f0, float f1, float f2, float f3) {
    unsigned short lo, hi;
    asm("cvt.rn.satfinite.e4m3x2.f32 %0, %1, %2;" : "=h"(lo) : "f"(f1), "f"(f0));
    asm("cvt.rn.satfinite.e4m3x2.f32 %0, %1, %2;" : "=h"(hi) : "f"(f3), "f"(f2));
    return (uint32_t)lo | ((uint32_t)hi << 16);
}

// ---------------- kernel 1: pooled = x.mean(axis=1), atomic-free --------------
// grid (B, 32): block handles 32 d's; 8 s-groups x 32 d-threads; smem reduce
__global__ void pooled_kernel(const float* __restrict__ x) {
    __shared__ float part[8][32];
    const int b = blockIdx.x;
    const int d0 = blockIdx.y * 32;
    const int dl = threadIdx.x & 31;           // d lane
    const int sg = threadIdx.x >> 5;           // s group (0..7)
    const float* p = x + ((size_t)b*Ssz + sg*512)*Dsz + d0 + dl;
    float acc = 0.f;
    #pragma unroll 4
    for (int s = 0; s < 512; s++) acc += p[(size_t)s*Dsz];
    part[sg][dl] = acc;
    __syncthreads();
    if (threadIdx.x < 32) {
        float t = part[0][dl] + part[1][dl] + part[2][dl] + part[3][dl]
                + part[4][dl] + part[5][dl] + part[6][dl] + part[7][dl];
        g_pooled[b*Dsz + d0 + dl] = t * (1.0f/(float)Ssz);
    }
}

// ---------------- kernel 1b: transpose W1 [h,d,g] -> [h,g,d] ------------------
__global__ void w1t_kernel(const float* __restrict__ W1) {
    __shared__ float t[32][33];
    const int h = blockIdx.z;
    const int g0 = blockIdx.x * 32, d0 = blockIdx.y * 32;
    const int tx = threadIdx.x & 31, ty = threadIdx.x >> 5;   // 32 x 8
    #pragma unroll
    for (int i = 0; i < 32; i += 8)
        t[ty + i][tx] = W1[h*Dsz*GHh + (d0 + ty + i)*GHh + g0 + tx];
    __syncthreads();
    #pragma unroll
    for (int i = 0; i < 32; i += 8)
        g_W1T[h*GHh*Dsz + (g0 + ty + i)*Dsz + d0 + tx] = t[tx][ty + i];
}

// ---------------- kernel 2a: hpre = relu(pooled @ W1 + b1) -------------------
__global__ void gate1_kernel(const float* __restrict__ b1) {
    const int h = blockIdx.x >> 7, g = blockIdx.x & 127;
    const int b = threadIdx.x >> 5, lane = threadIdx.x & 31;
    const float* w = g_W1T + (h*GHh + g)*Dsz;
    const float* p = g_pooled + b*Dsz;
    float a0 = 0.f, a1 = 0.f, a2 = 0.f, a3 = 0.f;
    #pragma unroll
    for (int d = lane; d < Dsz; d += 128) {
        a0 = fmaf(p[d      ], w[d      ], a0);
        a1 = fmaf(p[d + 32 ], w[d + 32 ], a1);
        a2 = fmaf(p[d + 64 ], w[d + 64 ], a2);
        a3 = fmaf(p[d + 96 ], w[d + 96 ], a3);
    }
    float acc = (a0 + a1) + (a2 + a3);
    #pragma unroll
    for (int o = 16; o; o >>= 1) acc += __shfl_xor_sync(0xffffffffu, acc, o);
    if (lane == 0)
        g_hpre[(h*Bsz + b)*GHh + g] = fmaxf(acc + b1[h*GHh + g], 0.f);
}

// ---------------- kernel 2b: logits/softmax; also zeroes g_dsum ---------------
__global__ void gate2_kernel(const float* __restrict__ W2, const float* __restrict__ b2) {
    const int h = blockIdx.x >> 2, b = blockIdx.x & 3;
    const int t = threadIdx.x;
    if (t == 0) g_dsum[blockIdx.x] = 0.f;      // hb == blockIdx.x; runs before density
    __shared__ float sh[GHh];
    __shared__ float part[128];
    sh[t] = g_hpre[(h*Bsz + b)*GHh + t];
    __syncthreads();
    const int m = t & 31, c = t >> 5;
    float acc = 0.f;
    #pragma unroll 8
    for (int i = 0; i < 32; i++) {
        const int g = c*32 + i;
        acc = fmaf(sh[g], W2[(h*GHh + g)*Mm + m], acc);
    }
    part[t] = acc;
    __syncthreads();
    if (t < 32) {
        float l = part[t] + part[t+32] + part[t+64] + part[t+96] + b2[h*Mm + t];
        float z = l * (1.0f/TEMP);
        float mx = z;
        #pragma unroll
        for (int o = 16; o; o >>= 1) mx = fmaxf(mx, __shfl_xor_sync(0xffffffffu, mx, o));
        float e = __expf(z - mx);
        float sm = e;
        #pragma unroll
        for (int o = 16; o; o >>= 1) sm += __shfl_xor_sync(0xffffffffu, sm, o);
        g_weights[(h*Bsz + b)*Mm + t] = e / sm;
    }
}

// ---------------- kernel 3: mask grids [H, M, S] ------------------------------
__global__ void mask_kernel(const float* __restrict__ freqs, const float* __restrict__ amps,
                            const float* __restrict__ phases) {
    const int hm = blockIdx.x;
    __shared__ float fx[Ww], fy[Ww], am[Ww], ph[Ww];
    if (threadIdx.x < Ww) {
        int w = threadIdx.x;
        fx[w] = freqs[(hm*Ww + w)*2 + 0];
        fy[w] = freqs[(hm*Ww + w)*2 + 1];
        am[w] = amps[hm*Ww + w];
        ph[w] = phases[hm*Ww + w];
    }
    __syncthreads();
    const float TWO_PI   = 6.28318530717958647692f;
    const float HALF_PI  = 1.57079632679489661923f;
    const float INV_2PI  = 0.15915494309189533577f;
    for (int s = threadIdx.x; s < Ssz; s += 256) {
        const int i = s >> 6, j = s & 63;
        const float px = -1.f + (float)j * (2.f/63.f);
        const float py = -1.f + (float)i * (2.f/63.f);
        float acc = 0.f;
        #pragma unroll
        for (int w = 0; w < Ww; w++) {
            float dot = fmaf(px, fx[w], py*fy[w]);
            float arg = fmaf(TWO_PI, dot, ph[w]);
            float t   = (arg - HALF_PI) * INV_2PI;
            float fr  = t - floorf(t);
            float tri01 = 1.f - 2.f*fabsf(fr - 0.5f);
            acc = fmaf(2.f*tri01 - 1.f, am[w], acc);
        }
        g_mask[hm*Ssz + s] = acc;
    }
}

// ---------------- kernel 4: final_grid + MC density (fused) -------------------
__global__ void density_kernel(const float* __restrict__ noise) {
    const int hb = blockIdx.y;
    const int h  = hb >> 2;
    const int s  = blockIdx.x*256 + threadIdx.x;
    __shared__ float wts[Mm];
    if (threadIdx.x < Mm) wts[threadIdx.x] = g_weights[hb*Mm + threadIdx.x];
    __syncthreads();

    const float* mk = g_mask + (h*Mm)*Ssz + s;
    float fg = 0.f;
    #pragma unroll
    for (int m = 0; m < Mm; m++) fg = fmaf(wts[m], mk[m*Ssz], fg);

    const float hfg = 0.5f * ALPHA * fg;
    const float hsn = 0.5f * ALPHA * SIGMA;
    const float* np = noise + (hb*NSs)*Ssz + s;
    float acc = 0.f;
    #pragma unroll 4
    for (int ns = 0; ns < NSs; ns++) {
        float z = fmaf(np[ns*Ssz], hsn, hfg);
        float t;
        asm("tanh.approx.f32 %0, %1;" : "=f"(t) : "f"(z));
        acc += t;
    }
    float dens = fmaf(acc, 0.5f/(float)NSs, 0.5f);
    g_dens[hb*Ssz + s] = dens;

    float v = dens;
    #pragma unroll
    for (int o = 16; o; o >>= 1) v += __shfl_xor_sync(0xffffffffu, v, o);
    __shared__ float red[8];
    if ((threadIdx.x & 31) == 0) red[threadIdx.x >> 5] = v;
    __syncthreads();
    if (threadIdx.x < 8) {
        float t = red[threadIdx.x];
        #pragma unroll
        for (int o = 4; o; o >>= 1) t += __shfl_xor_sync(0xffu, t, o);
        if (threadIdx.x == 0) atomicAdd(&g_dsum[hb], t);
    }
}

// ---------------- kernel 5: A' = x * dnorm * 4096 -> e4m3 ---------------------
__global__ void aprep8_kernel(const float* __restrict__ x) {
    const int gid = blockIdx.x*256 + threadIdx.x;     // BS*64 granules
    const int r = gid >> 6, g = gid & 63;             // row, k-granule (16 k each)
    const int hb = (g >> 3)*Bsz + (r >> 12);          // h = g>>3
    const float sc = g_dens[hb*Ssz + (r & 4095)] / (g_dsum[hb] + 1e-8f) * A_SCALE;
    const float4* xp = reinterpret_cast<const float4*>(x + (size_t)gid*16);
    float4 v0 = xp[0], v1 = xp[1], v2 = xp[2], v3 = xp[3];
    uint4 pk;
    pk.x = pack_fp8x4(v0.x*sc, v0.y*sc, v0.z*sc, v0.w*sc);
    pk.y = pack_fp8x4(v1.x*sc, v1.y*sc, v1.z*sc, v1.w*sc);
    pk.z = pack_fp8x4(v2.x*sc, v2.y*sc, v2.z*sc, v2.w*sc);
    pk.w = pack_fp8x4(v3.x*sc, v3.y*sc, v3.z*sc, v3.w*sc);
    *reinterpret_cast<uint4*>(g_A8 + (size_t)gid*16) = pk;
}

// ---------------- kernel 5b: transpose + convert Wo -> e4m3 [n][k], x64 -------
__global__ void wot8_kernel(const float* __restrict__ Wo) {
    __shared__ float t[32][33];
    const int n0 = blockIdx.x * 32, k0 = blockIdx.y * 32;
    const int tx = threadIdx.x & 31, ty = threadIdx.x >> 5;
    #pragma unroll
    for (int i = 0; i < 32; i += 8)
        t[ty + i][tx] = Wo[(k0 + ty + i)*Dsz + n0 + tx];
    __syncthreads();
    #pragma unroll
    for (int i = 0; i < 32; i += 8) {
        float v = t[tx][ty + i] * B_SCALE;
        unsigned short p;
        asm("cvt.rn.satfinite.e4m3x2.f32 %0, %1, %2;" : "=h"(p) : "f"(0.f), "f"(v));
        g_Wo8[(size_t)(n0 + ty + i)*Dsz + k0 + tx] = (uint8_t)(p & 0xFF);
    }
}

// ---------------- kernel 6: fp8 QMMA GEMM (fp16 accum) + bias + residual ------
// (measured-best R12 form: BK=64, register-staged double buffer)
#define BKP8 80        // padded k-stride in bytes (16B-aligned, conflict-free)
#define NKT8 (Dsz/64)  // 16 k-tiles

__global__ __launch_bounds__(256) void gemm_fp8_kernel(const float* __restrict__ x,
                                                       const float* __restrict__ bo,
                                                       float* __restrict__ out) {
    __shared__ __align__(16) uint8_t As[2][128][BKP8];   // [m][k]
    __shared__ __align__(16) uint8_t Bs[2][128][BKP8];   // [n][k]
    const int tid  = threadIdx.x;
    const int lane = tid & 31, warp = tid >> 5;
    const int mbase = (warp >> 2) * 64;          // warp grid 2 (m) x 4 (n)
    const int nbase = (warp & 3) * 32;
    const int rowBase = blockIdx.y * 128;
    const int colBase = blockIdx.x * 128;

    const int rA = tid >> 1;                     // loader row (0..127)
    const int halfA = tid & 1;                   // which 32-byte half
    const uint8_t* arow = g_A8  + (size_t)(rowBase + rA)*Dsz + halfA*32;
    const uint8_t* brow = g_Wo8 + (size_t)(colBase + rA)*Dsz + halfA*32;

    const uint32_t sA = (uint32_t)__cvta_generic_to_shared(&As[0][0][0]);
    const uint32_t sB = (uint32_t)__cvta_generic_to_shared(&Bs[0][0][0]);
    const uint32_t bufBytes = 128*BKP8;          // 10240

    const int lmA_row = mbase + (lane & 15);             // + mi*16
    const int lmA_colB = (lane >> 4) << 4;               // 0 or 16 bytes
    const int lmB_row = nbase + (lane & 7);              // + ni*8
    const int lmB_colB = ((lane >> 3) & 1) << 4;         // 0 or 16 bytes

    uint4 va[2], vb[2];

    {
        const uint4* ap = reinterpret_cast<const uint4*>(arow);
        va[0] = ap[0]; va[1] = ap[1];
        const uint4* bp = reinterpret_cast<const uint4*>(brow);
        vb[0] = bp[0]; vb[1] = bp[1];
        uint4* as = reinterpret_cast<uint4*>(&As[0][rA][halfA*32]);
        as[0] = va[0]; as[1] = va[1];
        uint4* bs = reinterpret_cast<uint4*>(&Bs[0][rA][halfA*32]);
        bs[0] = vb[0]; bs[1] = vb[1];
    }
    __syncthreads();
    {
        const uint4* ap = reinterpret_cast<const uint4*>(arow + 64);
        va[0] = ap[0]; va[1] = ap[1];
        const uint4* bp = reinterpret_cast<const uint4*>(brow + 64);
        vb[0] = bp[0]; vb[1] = bp[1];
    }

    uint32_t acc[4][4][2];
    #pragma unroll
    for (int mi = 0; mi < 4; mi++)
        #pragma unroll
        for (int ni = 0; ni < 4; ni++) { acc[mi][ni][0] = 0u; acc[mi][ni][1] = 0u; }

    for (int t = 0; t < NKT8; t++) {
        const int cur = t & 1;
        if (t + 1 < NKT8) {
            uint4* as = reinterpret_cast<uint4*>(&As[cur^1][rA][halfA*32]);
            as[0] = va[0]; as[1] = va[1];
            uint4* bs = reinterpret_cast<uint4*>(&Bs[cur^1][rA][halfA*32]);
            bs[0] = vb[0]; bs[1] = vb[1];
        }
        if (t + 2 < NKT8) {
            const uint4* ap = reinterpret_cast<const uint4*>(arow + (t+2)*64);
            va[0] = ap[0]; va[1] = ap[1];
            const uint4* bp = reinterpret_cast<const uint4*>(brow + (t+2)*64);
            vb[0] = bp[0]; vb[1] = bp[1];
        }
        const uint32_t aBase = sA + cur*bufBytes;
        const uint32_t bBase = sB + cur*bufBytes;
        #pragma unroll
        for (int ks = 0; ks < 2; ks++) {
            const int kB = ks * 32;
            uint32_t a[4][4], b[4][2];
            #pragma unroll
            for (int mi = 0; mi < 4; mi++) {
                uint32_t addr = aBase + (lmA_row + mi*16)*BKP8 + kB + lmA_colB;
                asm volatile("ldmatrix.sync.aligned.m8n8.x4.shared.b16 {%0,%1,%2,%3}, [%4];"
                             : "=r"(a[mi][0]), "=r"(a[mi][1]), "=r"(a[mi][2]), "=r"(a[mi][3])
                             : "r"(addr));
            }
            #pragma unroll
            for (int ni = 0; ni < 4; ni++) {
                uint32_t addr = bBase + (lmB_row + ni*8)*BKP8 + kB + lmB_colB;
                asm volatile("ldmatrix.sync.aligned.m8n8.x2.shared.b16 {%0,%1}, [%2];"
                             : "=r"(b[ni][0]), "=r"(b[ni][1])
                             : "r"(addr));
            }
            #pragma unroll
            for (int mi = 0; mi < 4; mi++)
                #pragma unroll
                for (int ni = 0; ni < 4; ni++) {
                    asm volatile(
                        "mma.sync.aligned.m16n8k32.row.col.f16.e4m3.e4m3.f16 "
                        "{%0,%1}, {%2,%3,%4,%5}, {%6,%7}, {%0,%1};"
                        : "+r"(acc[mi][ni][0]), "+r"(acc[mi][ni][1])
                        : "r"(a[mi][0]), "r"(a[mi][1]), "r"(a[mi][2]), "r"(a[mi][3]),
                          "r"(b[ni][0]), "r"(b[ni][1]));
                }
        }
        __syncthreads();
    }

    const int fr = lane >> 2;
    const int fc = (lane & 3) * 2;
    #pragma unroll
    for (int mi = 0; mi < 4; mi++) {
        const int r0 = rowBase + mbase + mi*16 + fr;
        #pragma unroll
        for (int ni = 0; ni < 4; ni++) {
            const int c0 = colBase + nbase + ni*8 + fc;
            float2 bov = *reinterpret_cast<const float2*>(bo + c0);
            float2 x0  = *reinterpret_cast<const float2*>(x + (size_t)r0*Dsz + c0);
            float2 x1  = *reinterpret_cast<const float2*>(x + (size_t)(r0+8)*Dsz + c0);
            __half2 h0 = *reinterpret_cast<__half2*>(&acc[mi][ni][0]);
            __half2 h1 = *reinterpret_cast<__half2*>(&acc[mi][ni][1]);
            float2 f0 = __half22float2(h0);
            float2 f1 = __half22float2(h1);
            float2 o0, o1;
            o0.x = f0.x*INV_SCALE + bov.x + x0.x;
            o0.y = f0.y*INV_SCALE + bov.y + x0.y;
            o1.x = f1.x*INV_SCALE + bov.x + x1.x;
            o1.y = f1.y*INV_SCALE + bov.y + x1.y;
            *reinterpret_cast<float2*>(out + (size_t)r0*Dsz + c0)     = o0;
            *reinterpret_cast<float2*>(out + (size_t)(r0+8)*Dsz + c0) = o1;
        }
    }
}

// ---------------- launcher ----------------------------------------------------
extern "C" void kernel_launch(void* const* d_in, const int* in_sizes, int n_in,
                              void* d_out, int out_size) {
    const float* x      = (const float*)d_in[0];
    const float* noise  = (const float*)d_in[1];
    const float* W1     = (const float*)d_in[2];
    const float* b1     = (const float*)d_in[3];
    const float* W2     = (const float*)d_in[4];
    const float* b2     = (const float*)d_in[5];
    const float* freqs  = (const float*)d_in[6];
    const float* amps   = (const float*)d_in[7];
    const float* phases = (const float*)d_in[8];
    const float* Wo     = (const float*)d_in[9];
    const float* bo     = (const float*)d_in[10];
    float* out = (float*)d_out;

    pooled_kernel  <<<dim3(Bsz, 32), 256>>>(x);
    wot8_kernel    <<<dim3(32, 32), 256>>>(Wo);
    w1t_kernel     <<<dim3(4, 32, 8), 256>>>(W1);
    gate1_kernel   <<<Hh*GHh, 128>>>(b1);
    gate2_kernel   <<<Hh*Bsz, 128>>>(W2, b2);
    mask_kernel    <<<Hh*Mm, 256>>>(freqs, amps, phases);
    density_kernel <<<dim3(Ssz/256, HB), 256>>>(noise);
    aprep8_kernel  <<<(BS*64)/256, 256>>>(x);
    gemm_fp8_kernel<<<dim3(Dsz/128, BS/128), 256>>>(x, bo, out);
}